// round 12
// baseline (speedup 1.0000x reference)
#include <cuda_runtime.h>
#include <cstdint>

#define G_    8
#define FG_   16
#define J_    8
#define W_    31
#define PAD1_ 15
#define L_    262144
#define KTILE_ 512
#define NTH_  256

// SMEM layout (32-bit words). yt ALIASES xs+ws (dead after main loop).
// xs shifted: xs[j][s] = x[kb + s - 16], s in [0,544); consumers read +1.
#define XS_PITCH 548
#define XS_ELEMS (J_ * XS_PITCH)         // 4384
#define WS_ELEMS (J_ * 4 * 32 * 4)       // 4096 words (uint4 slots)
#define YT_PITCH 516
#define YT_ELEMS (FG_ * YT_PITCH)        // 8256
#define SM_XS 0
#define SM_WS (SM_XS + XS_ELEMS)         // 4384
#define SM_YT 0
#define SMEM_WORDS (SM_WS + WS_ELEMS)    // 8480 words = 33920 B

// Pre-transformed weights: [g][slot] uint4-compatible, 32768 words = 128 KB.
__device__ uint32_t d_wt[G_ * WS_ELEMS];

__device__ __forceinline__ uint32_t cvt_tf32(float f) {
    uint32_t r;
    asm("cvt.rna.tf32.f32 %0, %1;" : "=r"(r) : "f"(f));
    return r;
}
__device__ __forceinline__ void cp16(uint32_t dst_smem, const void* src) {
    asm volatile("cp.async.cg.shared.global [%0], [%1], 16;"
                 :: "r"(dst_smem), "l"(src) : "memory");
}
#define CP_COMMIT() asm volatile("cp.async.commit_group;" ::: "memory")
#define CP_WAIT(N)  asm volatile("cp.async.wait_group " #N ";" ::: "memory")

__device__ __forceinline__ void mma_tf32(float d[4],
                                         uint32_t a0, uint32_t a1,
                                         uint32_t a2, uint32_t a3,
                                         uint32_t b0, uint32_t b1) {
    asm volatile(
        "mma.sync.aligned.m16n8k8.row.col.f32.tf32.tf32.f32 "
        "{%0,%1,%2,%3}, {%4,%5,%6,%7}, {%8,%9}, {%0,%1,%2,%3};"
        : "+f"(d[0]), "+f"(d[1]), "+f"(d[2]), "+f"(d[3])
        : "r"(a0), "r"(a1), "r"(a2), "r"(a3), "r"(b0), "r"(b1));
}

// Prep: transform params [g][f][j][w] -> d_wt uint4-slot image (rna tf32).
// slot = j*128 + w0g*32 + ln ; comp c: f = (c<2?0:8)+(ln>>2),
// w = w0g*8 + (ln&3) + (c&1)*4 (zero-pad w>=31).
__global__ void prep_w(const float* __restrict__ params) {
    int idx = blockIdx.x * blockDim.x + threadIdx.x;   // word index
    if (idx >= G_ * WS_ELEMS) return;
    int c    = idx & 3;
    int ln   = (idx >> 2) & 31;
    int w0g  = (idx >> 7) & 3;
    int j    = (idx >> 9) & 7;
    int g    = idx >> 12;
    int f    = ((c >> 1) << 3) + (ln >> 2);
    int w    = w0g * 8 + (ln & 3) + ((c & 1) << 2);
    float v  = (w < W_) ? params[((g * FG_ + f) * J_ + j) * W_ + w] : 0.f;
    d_wt[idx] = cvt_tf32(v);
}

// CTA: one group g, 512 consecutive k, 16 filters. Warp: 64 k x 16 f.
// A[m,kk] = xs[j][m + w0 + kk] (Toeplitz alias; X[22] register window).
// x raw-bit tf32 (HW truncation); weights rna (prep kernel).
// Staging: cp.async groups {ws, x_j0..x_j7}; j loop waits progressively.
__global__ void __launch_bounds__(NTH_, 4)
conv_mma(const float* __restrict__ x,
         const float* __restrict__ params,
         const int* __restrict__ rel,
         float* __restrict__ out)
{
    extern __shared__ uint32_t sm[];
    const uint32_t smb = (uint32_t)__cvta_generic_to_shared(sm);
    const int tid  = threadIdx.x;
    const int wid  = tid >> 5;
    const int lane = tid & 31;
    const int gid  = lane >> 2;
    const int tig  = lane & 3;
    const int g    = blockIdx.y;
    const int tile = blockIdx.x;
    const int kb   = tile * KTILE_;
    const int last = L_ / KTILE_ - 1;
    const bool interior = (tile != 0) && (tile != last);

    int rows[J_];
#pragma unroll
    for (int j = 0; j < J_; ++j) rows[j] = __ldg(rel + g * J_ + j);

    // ---- group 0: weights image, straight 16 KB copy ----
    {
        const uint32_t* src = d_wt + g * WS_ELEMS;
        for (int e = tid; e < WS_ELEMS / 4; e += NTH_)
            cp16(smb + (SM_WS + e * 4) * 4, src + e * 4);
        CP_COMMIT();
    }

    // ---- groups 1..8: x windows xs[j][s] = bits(x[kb + s - 16]) ----
    if (interior) {
#pragma unroll 1
        for (int j = 0; j < J_; ++j) {
            const char* xp = (const char*)(x + rows[j] * L_ + kb - 16);
            uint32_t xd = smb + (SM_XS + j * XS_PITCH) * 4;
            for (int q = tid; q < 136; q += NTH_)
                cp16(xd + 16 * q, xp + 16 * q);
            CP_COMMIT();
        }
    } else {
        // edge tiles: clamped scalar path (pollutes only overwritten outputs)
#pragma unroll 1
        for (int j = 0; j < J_; ++j) {
            const float* xr = x + rows[j] * L_;
            for (int s = tid; s < 544; s += NTH_) {
                int gi = kb + s - 16;
                gi = max(0, min(L_ - 1, gi));
                sm[SM_XS + j * XS_PITCH + s] = __float_as_uint(__ldg(xr + gi));
            }
        }
        CP_WAIT(0);
        __syncthreads();
    }

    const int warpk = wid * 64;

    float acc[4][2][4];
#pragma unroll
    for (int mi = 0; mi < 4; ++mi)
#pragma unroll
        for (int nh = 0; nh < 2; ++nh)
#pragma unroll
            for (int q = 0; q < 4; ++q) acc[mi][nh][q] = 0.f;

#pragma unroll
    for (int j = 0; j < J_; ++j) {
        if (interior) {
            // release group for this j (ws + x_j both complete)
            if      (j == 0) CP_WAIT(7);
            else if (j == 1) CP_WAIT(6);
            else if (j == 2) CP_WAIT(5);
            else if (j == 3) CP_WAIT(4);
            else if (j == 4) CP_WAIT(3);
            else if (j == 5) CP_WAIT(2);
            else if (j == 6) CP_WAIT(1);
            else             CP_WAIT(0);
            __syncthreads();
        }

        const uint32_t* xj = sm + SM_XS + j * XS_PITCH + 1 + warpk + gid + tig;
        const uint4* wj = (const uint4*)(sm + SM_WS + j * 512) + lane;

        uint32_t X[22];
#pragma unroll
        for (int i = 0; i < 22; ++i) X[i] = xj[4 * i];

        uint4 B = wj[0];
#pragma unroll
        for (int w0g = 0; w0g < 4; ++w0g) {
            uint4 Bn = wj[(w0g < 3 ? w0g + 1 : 3) * 32];
#pragma unroll
            for (int mi = 0; mi < 4; ++mi) {
                const int i0 = 4 * mi + 2 * w0g;
                mma_tf32(acc[mi][0], X[i0], X[i0 + 2], X[i0 + 1], X[i0 + 3], B.x, B.y);
                mma_tf32(acc[mi][1], X[i0], X[i0 + 2], X[i0 + 1], X[i0 + 3], B.z, B.w);
            }
            B = Bn;
        }
    }

    __syncthreads();   // xs/ws dead; yt aliases them

    // ---- D fragments -> yt[f][k], conflict-free (pitch 516) ----
    float* yt = (float*)(sm + SM_YT);
#pragma unroll
    for (int mi = 0; mi < 4; ++mi) {
        const int k0 = warpk + mi * 16 + gid;
#pragma unroll
        for (int nh = 0; nh < 2; ++nh) {
            const int f0 = nh * 8 + 2 * tig;
            yt[f0 * YT_PITCH + k0]           = acc[mi][nh][0];
            yt[(f0 + 1) * YT_PITCH + k0]     = acc[mi][nh][1];
            yt[f0 * YT_PITCH + k0 + 8]       = acc[mi][nh][2];
            yt[(f0 + 1) * YT_PITCH + k0 + 8] = acc[mi][nh][3];
        }
    }
    __syncthreads();

    // ---- coalesced float4 store ----
    for (int i = tid; i < FG_ * (KTILE_ / 4); i += NTH_) {
        int f  = i >> 7;
        int c4 = i & 127;
        float4 v = *(const float4*)(yt + f * YT_PITCH + c4 * 4);
        *(float4*)(out + (g * FG_ + f) * L_ + kb + c4 * 4) = v;
    }

    // ---- boundary overwrite (reference truncates; no zero-pad), full fp32 ----
    if (!interior) {
        __syncthreads();
        if (tid < FG_ * PAD1_) {
            const int f = tid / PAD1_;
            const int e = tid % PAD1_;
            const float* pk = params + (g * FG_ + f) * (J_ * W_);
            float s = 0.f;
            if (tile == 0) {
                for (int j = 0; j < J_; ++j) {
                    const float* xr = x + __ldg(rel + g * J_ + j) * L_;
                    for (int w = 0; w <= e + PAD1_; ++w)
                        s += xr[w] * pk[j * W_ + w];
                }
                out[(g * FG_ + f) * L_ + e] = s;
            } else {
                for (int j = 0; j < J_; ++j) {
                    const float* xr = x + __ldg(rel + g * J_ + j) * L_;
                    for (int w = e + 1; w < W_; ++w)
                        s += xr[L_ - W_ + w] * pk[j * W_ + w];
                }
                out[(g * FG_ + f) * L_ + (L_ - PAD1_ + e)] = s;
            }
        }
    }
}

extern "C" void kernel_launch(void* const* d_in, const int* in_sizes, int n_in,
                              void* d_out, int out_size)
{
    const float* x      = (const float*)d_in[0];
    const float* params = (const float*)d_in[1];
    const int*   rel    = (const int*)d_in[2];
    float* out = (float*)d_out;

    prep_w<<<(G_ * WS_ELEMS + 255) / 256, 256>>>(params);

    cudaFuncSetAttribute(conv_mma, cudaFuncAttributeMaxDynamicSharedMemorySize,
                         SMEM_WORDS * 4);
    dim3 grid(L_ / KTILE_, G_);   // 512 x 8
    conv_mma<<<grid, NTH_, SMEM_WORDS * 4>>>(x, params, rel, out);
}